// round 13
// baseline (speedup 1.0000x reference)
#include <cuda_runtime.h>
#include <cuda_bf16.h>
#include <cstdint>
#include <cstddef>

// Problem constants
#define BB   256
#define TT   1024
#define FF   64
#define HH   128
#define GG   512   // 4*H

using u64 = unsigned long long;

// ---------------------------------------------------------------------------
// Scratch (device globals; allocation in kernel_launch is forbidden)
// ---------------------------------------------------------------------------
__device__ float g_xg[(size_t)BB * TT * GG];   // 512 MB gate preactivations
__device__ float g_hs[(size_t)BB * TT * HH];   // 128 MB hidden states

// ---------------------------------------------------------------------------
// K1:  xg = x @ W_ih^T + (b_ih + b_hh)
//   Tile: 128 bt-rows x 64 gates, 256 threads, grid (2048, 8).
//   Thread = lane l (rows l,+32,+64,+96) x warp w (gates 8w..8w+7).
//   Per k per warp: 2 uniform LDS.128 + 4 LDS.32 vs 32 FFMA (ratio 5.3).
//   xs stored rotation-swizzled: col=(k+row)&63 -> conflict-free, no padding
//   (exactly 48 KB static smem with ws).
// ---------------------------------------------------------------------------
__global__ __launch_bounds__(256) void k1_xgemm(
    const float* __restrict__ x,
    const float* __restrict__ Wih,
    const float* __restrict__ bih,
    const float* __restrict__ bhh)
{
    __shared__ float xs[128][64];                 // [row][(k+row)&63], 32 KB
    __shared__ __align__(16) float ws[64][64];    // [k][gate], 16 KB

    const int bt0 = blockIdx.x * 128;
    const int g0  = blockIdx.y * 64;
    const int t   = threadIdx.x;
    const int l   = t & 31;           // lane -> base row
    const int w   = t >> 5;           // warp -> 8-gate group
    const int gl  = w * 8;            // local gate base (warp-uniform)

    // load x tile coalesced (128 rows x 64 k = 2048 float4), rotation store
    for (int i = t; i < 2048; i += 256) {
        int row = i >> 4;
        int kq  = i & 15;
        float4 v = ((const float4*)(x + (size_t)(bt0 + row) * FF))[kq];
        int k = kq * 4;
        xs[row][(k + 0 + row) & 63] = v.x;
        xs[row][(k + 1 + row) & 63] = v.y;
        xs[row][(k + 2 + row) & 63] = v.z;
        xs[row][(k + 3 + row) & 63] = v.w;
    }
    // load W tile transposed (64 gates x 64 k = 1024 float4)
    for (int i = t; i < 1024; i += 256) {
        int g  = i >> 4;
        int kq = i & 15;
        float4 v = ((const float4*)(Wih + (size_t)(g0 + g) * FF))[kq];
        int k = kq * 4;
        ws[k + 0][g] = v.x;
        ws[k + 1][g] = v.y;
        ws[k + 2][g] = v.z;
        ws[k + 3][g] = v.w;
    }

    // bias for my 8 gates (same for all 4 rows)
    float4 ba, bb;
    {
        float4 u = *(const float4*)(bih + g0 + gl);
        float4 v = *(const float4*)(bhh + g0 + gl);
        ba = make_float4(u.x + v.x, u.y + v.y, u.z + v.z, u.w + v.w);
        u = *(const float4*)(bih + g0 + gl + 4);
        v = *(const float4*)(bhh + g0 + gl + 4);
        bb = make_float4(u.x + v.x, u.y + v.y, u.z + v.z, u.w + v.w);
    }
    // acc[r*2+q]: row r, gate-quad q
    float4 acc[8];
#pragma unroll
    for (int r = 0; r < 4; r++) { acc[r * 2] = ba; acc[r * 2 + 1] = bb; }
    __syncthreads();

#pragma unroll 4
    for (int k = 0; k < 64; k++) {
        float4 wa = *(const float4*)&ws[k][gl];       // warp-uniform LDS.128
        float4 wb = *(const float4*)&ws[k][gl + 4];
        float xv[4];
        xv[0] = xs[l][(k + l) & 63];                  // conflict-free LDS.32
        xv[1] = xs[l + 32][(k + l + 32) & 63];
        xv[2] = xs[l + 64][(k + l + 64) & 63];
        xv[3] = xs[l + 96][(k + l + 96) & 63];
#pragma unroll
        for (int r = 0; r < 4; r++) {
            float xr = xv[r];
            acc[r*2].x   += xr * wa.x; acc[r*2].y   += xr * wa.y;
            acc[r*2].z   += xr * wa.z; acc[r*2].w   += xr * wa.w;
            acc[r*2+1].x += xr * wb.x; acc[r*2+1].y += xr * wb.y;
            acc[r*2+1].z += xr * wb.z; acc[r*2+1].w += xr * wb.w;
        }
    }

    // store 8 gates for 4 rows (2x STG.128 per row)
    const size_t gcol = (size_t)(g0 + gl);
#pragma unroll
    for (int r = 0; r < 4; r++) {
        float* outp = g_xg + (size_t)(bt0 + l + 32 * r) * GG + gcol;
        *(float4*)(outp)     = acc[r * 2];
        *(float4*)(outp + 4) = acc[r * 2 + 1];
    }
}

// ---------------------------------------------------------------------------
// K2: persistent LSTM recurrence, 64 clusters x 2 CTAs, TWO row-groups per
//   cluster pipelined against the two barrier.cluster phases per step:
//     A(g0) route0 sync arrive | A(g1) route1 wait sync arrive |
//     pw(g0 by t<128) wait | pw(g1 by t in [128,256)) sync
//   pbuf for g0 is parity double-buffered (route0(t+1) races peer pw0(t));
//   pbuf g1 single-buffered (provably ordered). Scalar FFMA + MUFU pointwise.
// ---------------------------------------------------------------------------
__device__ __forceinline__ float fsigm(float v) {
    return __fdividef(1.0f, 1.0f + __expf(-v));
}
__device__ __forceinline__ float ftanh(float v) {
    return 1.0f - __fdividef(2.0f, 1.0f + __expf(2.0f * v));
}

__global__ __launch_bounds__(512, 1) __cluster_dims__(2, 1, 1)
void k2_lstm(const float* __restrict__ Whh)
{
    __shared__ __align__(16) float hbuf[2][64][2];           // [grp][kLocal][row]
    __shared__ __align__(16) float pbuf0[2][2][4][64][2];    // [par][src][gt][j][row] 8KB
    __shared__ __align__(16) float pbuf1[2][4][64][2];       //      [src][gt][j][row] 4KB

    const int t    = threadIdx.x;          // == global gate index
    const int rank = blockIdx.x & 1;
    const int cid  = blockIdx.x >> 1;
    const int rowBase = cid * 4;
    const int kOff = rank * 64;

    // --- load my W_hh row-half into registers ---
    float w[64];
    {
        const float4* wp = (const float4*)(Whh + (size_t)t * HH + kOff);
#pragma unroll
        for (int q = 0; q < 16; q++) {
            float4 v = wp[q];
            w[4 * q + 0] = v.x;
            w[4 * q + 1] = v.y;
            w[4 * q + 2] = v.z;
            w[4 * q + 3] = v.w;
        }
    }

    // gate decomposition for partial routing
    const int gt    = t >> 7;        // gate type 0..3 (i,f,g,o)
    const int jg    = t & 127;       // h column of this gate
    const int owner = jg >> 6;       // owning CTA of that h column
    const int jl    = jg & 63;       // column local to owner
    const bool remote = (owner != rank);

    float* dst0 = &pbuf0[0][rank][gt][jl][0];
    float* dst1 = &pbuf1[rank][gt][jl][0];
    uint32_t rAddr0 = 0, rAddr1 = 0;
    if (remote) {
        uint32_t la0 = (uint32_t)__cvta_generic_to_shared(dst0);
        uint32_t la1 = (uint32_t)__cvta_generic_to_shared(dst1);
        asm volatile("mapa.shared::cluster.u32 %0, %1, %2;"
                     : "=r"(rAddr0) : "r"(la0), "r"(owner));
        asm volatile("mapa.shared::cluster.u32 %0, %1, %2;"
                     : "=r"(rAddr1) : "r"(la1), "r"(owner));
    }
    const uint32_t PAR0_STRIDE = 2u * 4u * 64u * 2u * 4u;   // 4096 B (pbuf0 parity)

    // pointwise identity (t < 256): grp = t>>7, item u = t&127 -> (pj, pr)
    const int pgrp = (t >> 7) & 1;
    const int pu   = t & 127;
    const int pj   = pu >> 1;        // owned h column (local)
    const int pr   = pu & 1;         // row within group
    const int pb   = rowBase + 2 * pgrp + pr;   // global batch row

    if (t < 256) hbuf[pgrp][pj][pr] = 0.0f;
    float c = 0.0f;
    __syncthreads();

    for (int step = 0; step < TT; step++) {
        const int par = step & 1;

        // prefetch this step's xg for my 4 owned gates (hidden under phase A)
        float xg0 = 0.f, xg1 = 0.f, xg2 = 0.f, xg3 = 0.f;
        if (t < 256) {
            size_t base = ((size_t)pb * TT + step) * GG + (size_t)(rank * 64 + pj);
            xg0 = g_xg[base];
            xg1 = g_xg[base + 128];
            xg2 = g_xg[base + 256];
            xg3 = g_xg[base + 384];
        }

        // --- A(g0): 2-row split-K dot products ---
        float a0 = 0.f, a1 = 0.f;
#pragma unroll
        for (int k = 0; k < 64; k++) {
            float2 hv = *(const float2*)&hbuf[0][k][0];   // broadcast LDS.64
            a0 += w[k] * hv.x;
            a1 += w[k] * hv.y;
        }
        if (!remote) {
            *(float2*)((char*)dst0 + par * PAR0_STRIDE) = make_float2(a0, a1);
        } else {
            uint32_t a = rAddr0 + par * PAR0_STRIDE;
            asm volatile("st.shared::cluster.f32 [%0], %1;" :: "r"(a),     "f"(a0) : "memory");
            asm volatile("st.shared::cluster.f32 [%0], %1;" :: "r"(a + 4), "f"(a1) : "memory");
        }
        __syncthreads();                                   // local pbuf0 visible
        asm volatile("barrier.cluster.arrive.aligned;" ::: "memory");   // phase p

        // --- A(g1) (hides phase-p release latency) ---
        float b0 = 0.f, b1 = 0.f;
#pragma unroll
        for (int k = 0; k < 64; k++) {
            float2 hv = *(const float2*)&hbuf[1][k][0];
            b0 += w[k] * hv.x;
            b1 += w[k] * hv.y;
        }
        if (!remote) {
            *(float2*)dst1 = make_float2(b0, b1);
        } else {
            asm volatile("st.shared::cluster.f32 [%0], %1;" :: "r"(rAddr1),     "f"(b0) : "memory");
            asm volatile("st.shared::cluster.f32 [%0], %1;" :: "r"(rAddr1 + 4), "f"(b1) : "memory");
        }
        asm volatile("barrier.cluster.wait.aligned;" ::: "memory");     // p: peer pbuf0 ready
        __syncthreads();                                   // local pbuf1 visible
        asm volatile("barrier.cluster.arrive.aligned;" ::: "memory");   // phase p+1

        // --- pw(g0) by threads 0..127 (overlaps phase-(p+1) release) ---
        if (t < 128) {
            const float (*pb0)[4][64][2] = &pbuf0[par][0];
            float gi = xg0 + pb0[0][0][pj][pr] + pb0[1][0][pj][pr];
            float gf = xg1 + pb0[0][1][pj][pr] + pb0[1][1][pj][pr];
            float gc = xg2 + pb0[0][2][pj][pr] + pb0[1][2][pj][pr];
            float go = xg3 + pb0[0][3][pj][pr] + pb0[1][3][pj][pr];
            float iv = fsigm(gi), fv = fsigm(gf), gv = ftanh(gc), ov = fsigm(go);
            c = fv * c + iv * gv;
            float h = ov * ftanh(c);
            hbuf[0][pj][pr] = h;
            g_hs[((size_t)pb * TT + step) * HH + (size_t)(rank * 64 + pj)] = h;
        }
        asm volatile("barrier.cluster.wait.aligned;" ::: "memory");     // p+1: peer pbuf1 ready

        // --- pw(g1) by threads 128..255 ---
        if (t >= 128 && t < 256) {
            float gi = xg0 + pbuf1[0][0][pj][pr] + pbuf1[1][0][pj][pr];
            float gf = xg1 + pbuf1[0][1][pj][pr] + pbuf1[1][1][pj][pr];
            float gc = xg2 + pbuf1[0][2][pj][pr] + pbuf1[1][2][pj][pr];
            float go = xg3 + pbuf1[0][3][pj][pr] + pbuf1[1][3][pj][pr];
            float iv = fsigm(gi), fv = fsigm(gf), gv = ftanh(gc), ov = fsigm(go);
            c = fv * c + iv * gv;
            float h = ov * ftanh(c);
            hbuf[1][pj][pr] = h;
            g_hs[((size_t)pb * TT + step) * HH + (size_t)(rank * 64 + pj)] = h;
        }
        __syncthreads();   // h (both groups) visible before next phase A
    }
}

// ---------------------------------------------------------------------------
// K3: out = hs @ W_out^T.  hs: [BT, 128], W_out: [64, 128].  (R3 verbatim)
// ---------------------------------------------------------------------------
__global__ __launch_bounds__(256) void k3_proj(
    const float* __restrict__ Wout,
    float* __restrict__ out)
{
    __shared__ __align__(16) float hs_s[32][128];   // 16 KB
    __shared__ __align__(16) float ws[128][64];     // 32 KB, [k][f] transposed

    const int bt0 = blockIdx.x * 32;
    const int t   = threadIdx.x;

    for (int i = t; i < 1024; i += 256) {
        int row = i >> 5;
        int q   = i & 31;
        ((float4*)hs_s[row])[q] =
            ((const float4*)(g_hs + (size_t)(bt0 + row) * HH))[q];
    }
    for (int i = t; i < 2048; i += 256) {
        int f  = i >> 5;
        int kq = i & 31;
        float4 v = ((const float4*)(Wout + (size_t)f * HH))[kq];
        int k = kq * 4;
        ws[k + 0][f] = v.x;
        ws[k + 1][f] = v.y;
        ws[k + 2][f] = v.z;
        ws[k + 3][f] = v.w;
    }
    __syncthreads();

    const int tf = t & 15;
    const int tr = t >> 4;

    float4 acc0 = make_float4(0.f, 0.f, 0.f, 0.f);
    float4 acc1 = make_float4(0.f, 0.f, 0.f, 0.f);

#pragma unroll
    for (int k = 0; k < 128; k++) {
        float4 w4 = *(float4*)&ws[k][tf * 4];
        float h0 = hs_s[tr][k];
        float h1 = hs_s[tr + 16][k];
        acc0.x += h0 * w4.x; acc0.y += h0 * w4.y;
        acc0.z += h0 * w4.z; acc0.w += h0 * w4.w;
        acc1.x += h1 * w4.x; acc1.y += h1 * w4.y;
        acc1.z += h1 * w4.z; acc1.w += h1 * w4.w;
    }

    *(float4*)(out + (size_t)(bt0 + tr) * FF + tf * 4)      = acc0;
    *(float4*)(out + (size_t)(bt0 + tr + 16) * FF + tf * 4) = acc1;
}

// ---------------------------------------------------------------------------
// launch
// ---------------------------------------------------------------------------
extern "C" void kernel_launch(void* const* d_in, const int* in_sizes, int n_in,
                              void* d_out, int out_size)
{
    const float* x    = (const float*)d_in[0];  // [256,1024,64]
    const float* Wih  = (const float*)d_in[1];  // [512,64]
    const float* Whh  = (const float*)d_in[2];  // [512,128]
    const float* bih  = (const float*)d_in[3];  // [512]
    const float* bhh  = (const float*)d_in[4];  // [512]
    const float* Wout = (const float*)d_in[5];  // [64,128]
    float* out = (float*)d_out;                 // [256,1024,64]

    (void)in_sizes; (void)n_in; (void)out_size;

    k1_xgemm<<<dim3((BB * TT) / 128, 8), 256>>>(x, Wih, bih, bhh);
    k2_lstm<<<128, 512>>>(Whh);
    k3_proj<<<(BB * TT) / 32, 256>>>(Wout, out);
}

// round 16
// speedup vs baseline: 1.1506x; 1.1506x over previous
#include <cuda_runtime.h>
#include <cuda_bf16.h>
#include <cstdint>
#include <cstddef>

#define BB 256
#define TT 1024
#define FF 64
#define HH 128
#define GG 512
using u64 = unsigned long long;

__device__ float g_xg[(size_t)BB * TT * GG];
__device__ float g_hs[(size_t)BB * TT * HH];

// ---------------- K1 (R12 verbatim, 658us measured) ----------------
__global__ __launch_bounds__(256) void k1_xgemm(
    const float* __restrict__ x, const float* __restrict__ Wih,
    const float* __restrict__ bih, const float* __restrict__ bhh)
{
    __shared__ float xs[128][64];
    __shared__ __align__(16) float ws[64][64];
    const int bt0 = blockIdx.x * 128, g0 = blockIdx.y * 64, t = threadIdx.x;
    const int l = t & 31, w = t >> 5, gl = w * 8;
    for (int i = t; i < 2048; i += 256) {
        int row = i >> 4, kq = i & 15;
        float4 v = ((const float4*)(x + (size_t)(bt0 + row) * FF))[kq];
        int k = kq * 4;
        xs[row][(k + 0 + row) & 63] = v.x; xs[row][(k + 1 + row) & 63] = v.y;
        xs[row][(k + 2 + row) & 63] = v.z; xs[row][(k + 3 + row) & 63] = v.w;
    }
    for (int i = t; i < 1024; i += 256) {
        int g = i >> 4, kq = i & 15;
        float4 v = ((const float4*)(Wih + (size_t)(g0 + g) * FF))[kq];
        int k = kq * 4;
        ws[k][g] = v.x; ws[k + 1][g] = v.y; ws[k + 2][g] = v.z; ws[k + 3][g] = v.w;
    }
    float4 ba, bb;
    {
        float4 u = *(const float4*)(bih + g0 + gl), v = *(const float4*)(bhh + g0 + gl);
        ba = make_float4(u.x + v.x, u.y + v.y, u.z + v.z, u.w + v.w);
        u = *(const float4*)(bih + g0 + gl + 4); v = *(const float4*)(bhh + g0 + gl + 4);
        bb = make_float4(u.x + v.x, u.y + v.y, u.z + v.z, u.w + v.w);
    }
    float4 acc[8];
#pragma unroll
    for (int r = 0; r < 4; r++) { acc[r * 2] = ba; acc[r * 2 + 1] = bb; }
    __syncthreads();
#pragma unroll 4
    for (int k = 0; k < 64; k++) {
        float4 wa = *(const float4*)&ws[k][gl], wb = *(const float4*)&ws[k][gl + 4];
        float xv[4];
        xv[0] = xs[l][(k + l) & 63];           xv[1] = xs[l + 32][(k + l + 32) & 63];
        xv[2] = xs[l + 64][(k + l + 64) & 63]; xv[3] = xs[l + 96][(k + l + 96) & 63];
#pragma unroll
        for (int r = 0; r < 4; r++) {
            float xr = xv[r];
            acc[r*2].x += xr*wa.x; acc[r*2].y += xr*wa.y; acc[r*2].z += xr*wa.z; acc[r*2].w += xr*wa.w;
            acc[r*2+1].x += xr*wb.x; acc[r*2+1].y += xr*wb.y; acc[r*2+1].z += xr*wb.z; acc[r*2+1].w += xr*wb.w;
        }
    }
    const size_t gcol = (size_t)(g0 + gl);
#pragma unroll
    for (int r = 0; r < 4; r++) {
        float* outp = g_xg + (size_t)(bt0 + l + 32 * r) * GG + gcol;
        *(float4*)(outp) = acc[r * 2]; *(float4*)(outp + 4) = acc[r * 2 + 1];
    }
}

// ---------------- K2: warp-level bf16 MMA recurrence (sm_100-safe) ----------
__device__ __forceinline__ float fsigm(float v) { return __fdividef(1.0f, 1.0f + __expf(-v)); }
__device__ __forceinline__ float ftanh(float v) { return 1.0f - __fdividef(2.0f, 1.0f + __expf(2.0f * v)); }

#define MMA16816(d0,d1,d2,d3,a,b0,b1) \
    asm volatile("mma.sync.aligned.m16n8k16.row.col.f32.bf16.bf16.f32 " \
        "{%0,%1,%2,%3},{%4,%5,%6,%7},{%8,%9},{%0,%1,%2,%3};" \
        : "+f"(d0), "+f"(d1), "+f"(d2), "+f"(d3) \
        : "r"((a)[0]), "r"((a)[1]), "r"((a)[2]), "r"((a)[3]), "r"(b0), "r"(b1))

__global__ void __launch_bounds__(512, 1) __cluster_dims__(2, 1, 1)
k2_lstm_mma(const float* __restrict__ Whh)
{
    // h buffers: [parity][n(8 rows)][k(128, pad 136)] bf16, hi and lo
    __shared__ __align__(16) unsigned short hhi[2][8][136];
    __shared__ __align__(16) unsigned short hlo[2][8][136];
    __shared__ __align__(16) float actbuf[4][64][8];   // [type][j_loc][n]

    const int t = threadIdx.x;
    const int w = t >> 5, lane = t & 31;
    const int gr = lane >> 2, tg = lane & 3;
    uint32_t rank; asm("mov.u32 %0, %%cluster_ctarank;" : "=r"(rank));
    const int row0 = (blockIdx.x >> 1) * 8;
    const int type = w >> 2;          // gate type of my warp
    const int jb   = (w & 3) * 16;    // local j base of my warp

    // --- A fragments: Whh rows (permuted: type, j_glob) -> bf16 hi/lo, persistent
    uint32_t aHi[8][4], aLo[8][4];
#pragma unroll
    for (int ch = 0; ch < 8; ch++) {
#pragma unroll
        for (int r = 0; r < 4; r++) {
            int m = gr + ((r & 1) ? 8 : 0);
            int k = ch * 16 + tg * 2 + ((r >> 1) ? 8 : 0);
            int gate = type * 128 + 64 * (int)rank + jb + m;
            float w0 = Whh[gate * 128 + k];
            float w1 = Whh[gate * 128 + k + 1];
            __nv_bfloat16 h0 = __float2bfloat16(w0);
            __nv_bfloat16 h1 = __float2bfloat16(w1);
            __nv_bfloat16 l0 = __float2bfloat16(w0 - __bfloat162float(h0));
            __nv_bfloat16 l1 = __float2bfloat16(w1 - __bfloat162float(h1));
            aHi[ch][r] = (uint32_t)*(unsigned short*)&h0 | ((uint32_t)*(unsigned short*)&h1 << 16);
            aLo[ch][r] = (uint32_t)*(unsigned short*)&l0 | ((uint32_t)*(unsigned short*)&l1 << 16);
        }
    }

    // peer smem base addresses
    uint32_t peerHHI, peerHLO;
    {
        uint32_t la = (uint32_t)__cvta_generic_to_shared(&hhi[0][0][0]);
        asm("mapa.shared::cluster.u32 %0, %1, %2;" : "=r"(peerHHI) : "r"(la), "r"(1u - rank));
        la = (uint32_t)__cvta_generic_to_shared(&hlo[0][0][0]);
        asm("mapa.shared::cluster.u32 %0, %1, %2;" : "=r"(peerHLO) : "r"(la), "r"(1u - rank));
    }

    // zero h buffers (h0 = 0), init c
    for (int i = t; i < 2 * 8 * 136; i += 512) {
        ((unsigned short*)hhi)[i] = 0;
        ((unsigned short*)hlo)[i] = 0;
    }
    float c = 0.f;
    // pointwise identity: thread -> (j_loc, n)
    const int pj = t >> 3;
    const int pn = t & 7;
    const int jglob = 64 * (int)rank + pj;
    __syncthreads();
    asm volatile("barrier.cluster.arrive.aligned;" ::: "memory");
    asm volatile("barrier.cluster.wait.aligned;"   ::: "memory");

    // mma epilogue identity
    const int gate0 = type * 128 + 64 * (int)rank + jb + gr;
    const int gate1 = gate0 + 8;
    const int n0 = tg * 2;

    for (int step = 0; step < TT; step++) {
        const int par = step & 1;

        // xg prefetch (overlaps MMA; consumed after)
        float xg00 = g_xg[((size_t)(row0 + n0)     * TT + step) * GG + gate0];
        float xg01 = g_xg[((size_t)(row0 + n0 + 1) * TT + step) * GG + gate0];
        float xg10 = g_xg[((size_t)(row0 + n0)     * TT + step) * GG + gate1];
        float xg11 = g_xg[((size_t)(row0 + n0 + 1) * TT + step) * GG + gate1];

        // D = Whi*hhi (chain A) ;  Whi*hlo + Wlo*hhi (chain B)
        float dA0 = 0.f, dA1 = 0.f, dA2 = 0.f, dA3 = 0.f;
        float dB0 = 0.f, dB1 = 0.f, dB2 = 0.f, dB3 = 0.f;
#pragma unroll
        for (int ch = 0; ch < 8; ch++) {
            uint32_t bh0 = *(const uint32_t*)&hhi[par][gr][ch * 16 + tg * 2];
            uint32_t bh1 = *(const uint32_t*)&hhi[par][gr][ch * 16 + 8 + tg * 2];
            uint32_t bl0 = *(const uint32_t*)&hlo[par][gr][ch * 16 + tg * 2];
            uint32_t bl1 = *(const uint32_t*)&hlo[par][gr][ch * 16 + 8 + tg * 2];
            MMA16816(dA0, dA1, dA2, dA3, aHi[ch], bh0, bh1);
            MMA16816(dB0, dB1, dB2, dB3, aHi[ch], bl0, bl1);
            MMA16816(dB0, dB1, dB2, dB3, aLo[ch], bh0, bh1);
        }

        // activations (lane owns (m=gr, n0), (gr, n0+1), (gr+8, n0), (gr+8, n0+1))
        float v00 = dA0 + dB0 + xg00;
        float v01 = dA1 + dB1 + xg01;
        float v10 = dA2 + dB2 + xg10;
        float v11 = dA3 + dB3 + xg11;
        if (type == 2) {
            v00 = ftanh(v00); v01 = ftanh(v01); v10 = ftanh(v10); v11 = ftanh(v11);
        } else {
            v00 = fsigm(v00); v01 = fsigm(v01); v10 = fsigm(v10); v11 = fsigm(v11);
        }
        actbuf[type][jb + gr][n0]         = v00;
        actbuf[type][jb + gr][n0 + 1]     = v01;
        actbuf[type][jb + gr + 8][n0]     = v10;
        actbuf[type][jb + gr + 8][n0 + 1] = v11;
        __syncthreads();

        // pointwise: one (j, n) pair per thread, c in register
        {
            float iv = actbuf[0][pj][pn];
            float fv = actbuf[1][pj][pn];
            float gv = actbuf[2][pj][pn];
            float ov = actbuf[3][pj][pn];
            c = fv * c + iv * gv;
            float h = ov * ftanh(c);
            g_hs[((size_t)(row0 + pn) * TT + step) * HH + jglob] = h;

            __nv_bfloat16 hh = __float2bfloat16(h);
            __nv_bfloat16 hl = __float2bfloat16(h - __bfloat162float(hh));
            unsigned short hb = *(unsigned short*)&hh;
            unsigned short lb = *(unsigned short*)&hl;
            const int wpar = par ^ 1;
            hhi[wpar][pn][jglob] = hb;
            hlo[wpar][pn][jglob] = lb;
            uint32_t off = (uint32_t)(((wpar * 8 + pn) * 136 + jglob) * 2);
            asm volatile("st.shared::cluster.b16 [%0], %1;" :: "r"(peerHHI + off), "h"(hb) : "memory");
            asm volatile("st.shared::cluster.b16 [%0], %1;" :: "r"(peerHLO + off), "h"(lb) : "memory");
        }
        __syncthreads();   // local h[wpar] + actbuf reuse ordering
        asm volatile("barrier.cluster.arrive.aligned;" ::: "memory");
        asm volatile("barrier.cluster.wait.aligned;"   ::: "memory");
    }
}

// ---------------- K3 (R3 verbatim) ----------------
__global__ __launch_bounds__(256) void k3_proj(
    const float* __restrict__ Wout, float* __restrict__ out)
{
    __shared__ __align__(16) float hs_s[32][128];
    __shared__ __align__(16) float ws[128][64];
    const int bt0 = blockIdx.x * 32, t = threadIdx.x;
    for (int i = t; i < 1024; i += 256) {
        int row = i >> 5, q = i & 31;
        ((float4*)hs_s[row])[q] = ((const float4*)(g_hs + (size_t)(bt0 + row) * HH))[q];
    }
    for (int i = t; i < 2048; i += 256) {
        int f = i >> 5, kq = i & 31;
        float4 v = ((const float4*)(Wout + (size_t)f * HH))[kq];
        int k = kq * 4;
        ws[k][f] = v.x; ws[k + 1][f] = v.y; ws[k + 2][f] = v.z; ws[k + 3][f] = v.w;
    }
    __syncthreads();
    const int tf = t & 15, tr = t >> 4;
    float4 acc0 = make_float4(0.f, 0.f, 0.f, 0.f), acc1 = acc0;
#pragma unroll
    for (int k = 0; k < 128; k++) {
        float4 w4 = *(float4*)&ws[k][tf * 4];
        float h0 = hs_s[tr][k], h1 = hs_s[tr + 16][k];
        acc0.x += h0 * w4.x; acc0.y += h0 * w4.y; acc0.z += h0 * w4.z; acc0.w += h0 * w4.w;
        acc1.x += h1 * w4.x; acc1.y += h1 * w4.y; acc1.z += h1 * w4.z; acc1.w += h1 * w4.w;
    }
    *(float4*)(out + (size_t)(bt0 + tr) * FF + tf * 4) = acc0;
    *(float4*)(out + (size_t)(bt0 + tr + 16) * FF + tf * 4) = acc1;
}

extern "C" void kernel_launch(void* const* d_in, const int* in_sizes, int n_in,
                              void* d_out, int out_size)
{
    const float* x    = (const float*)d_in[0];
    const float* Wih  = (const float*)d_in[1];
    const float* Whh  = (const float*)d_in[2];
    const float* bih  = (const float*)d_in[3];
    const float* bhh  = (const float*)d_in[4];
    const float* Wout = (const float*)d_in[5];
    float* out = (float*)d_out;
    (void)in_sizes; (void)n_in; (void)out_size;

    k1_xgemm<<<dim3((BB * TT) / 128, 8), 256>>>(x, Wih, bih, bhh);
    k2_lstm_mma<<<64, 512>>>(Whh);
    k3_proj<<<(BB * TT) / 32, 256>>>(Wout, out);
}

// round 17
// speedup vs baseline: 1.3318x; 1.1574x over previous
#include <cuda_runtime.h>
#include <cuda_bf16.h>
#include <cstdint>
#include <cstddef>

#define BB 256
#define TT 1024
#define FF 64
#define HH 128
#define GG 512
using u64 = unsigned long long;

__device__ float g_hs[(size_t)BB * TT * HH];   // hidden states for k3

__device__ __forceinline__ float fsigm(float v) { return __fdividef(1.0f, 1.0f + __expf(-v)); }
__device__ __forceinline__ float ftanh(float v) { return 1.0f - __fdividef(2.0f, 1.0f + __expf(2.0f * v)); }

#define MMA16816(d0,d1,d2,d3,a,b0,b1) \
    asm volatile("mma.sync.aligned.m16n8k16.row.col.f32.bf16.bf16.f32 " \
        "{%0,%1,%2,%3},{%4,%5,%6,%7},{%8,%9},{%0,%1,%2,%3};" \
        : "+f"(d0), "+f"(d1), "+f"(d2), "+f"(d3) \
        : "r"((a)[0]), "r"((a)[1]), "r"((a)[2]), "r"((a)[3]), "r"(b0), "r"(b1))

// ---------------------------------------------------------------------------
// K2: fused LSTM. 32 clusters x 2 CTAs x 256 thr. Cluster owns 8 batch rows.
//   CTA rank r owns h-cols [64r,64r+64) with all 4 gate types (M-split,
//   full K -> only h exchanged). Warp w: type=w>>1, jb=(w&1)*32, M=32.
//   gates = x@Wih^T (K=64, from per-step xbuf) + h@Whh^T (K=128) + bias,
//   all via bf16 split-precision HMMA (3 terms), fp32 accum.
// ---------------------------------------------------------------------------
__global__ void __launch_bounds__(256, 1) __cluster_dims__(2, 1, 1)
k2_lstm_fused(const float* __restrict__ x,
              const float* __restrict__ Wih,
              const float* __restrict__ Whh,
              const float* __restrict__ bih,
              const float* __restrict__ bhh)
{
    __shared__ __align__(16) unsigned short hhi[2][8][136];  // [par][n][k]
    __shared__ __align__(16) unsigned short hlo[2][8][136];
    __shared__ __align__(16) unsigned short xhi[2][8][72];   // [par][n][f]
    __shared__ __align__(16) unsigned short xlo[2][8][72];
    __shared__ __align__(16) float actbuf[4][64][8];         // [type][j][n]

    const int t = threadIdx.x;
    const int w = t >> 5, lane = t & 31;
    const int gr = lane >> 2, tg = lane & 3;
    uint32_t rank; asm("mov.u32 %0, %%cluster_ctarank;" : "=r"(rank));
    const int row0 = (blockIdx.x >> 1) * 8;
    const int type = w >> 1;              // gate type of my warp
    const int jb   = (w & 1) * 32;        // local j base (32 wide)
    const int gbase = type * 128 + 64 * (int)rank + jb;

    // --- A fragments: Whh (K=128, 8 chunks) and Wih (K=64, 4 chunks), 2 m-tiles
    uint32_t aH[2][8][4], aL[2][8][4], iH[2][4][4], iL[2][4][4];
#pragma unroll
    for (int mt = 0; mt < 2; mt++) {
#pragma unroll
        for (int ch = 0; ch < 8; ch++) {
#pragma unroll
            for (int r = 0; r < 4; r++) {
                int gate = gbase + mt * 16 + gr + ((r & 1) ? 8 : 0);
                int k = ch * 16 + tg * 2 + ((r >> 1) ? 8 : 0);
                float w0 = Whh[gate * HH + k], w1 = Whh[gate * HH + k + 1];
                __nv_bfloat16 h0 = __float2bfloat16(w0), h1 = __float2bfloat16(w1);
                __nv_bfloat16 l0 = __float2bfloat16(w0 - __bfloat162float(h0));
                __nv_bfloat16 l1 = __float2bfloat16(w1 - __bfloat162float(h1));
                aH[mt][ch][r] = (uint32_t)*(unsigned short*)&h0 | ((uint32_t)*(unsigned short*)&h1 << 16);
                aL[mt][ch][r] = (uint32_t)*(unsigned short*)&l0 | ((uint32_t)*(unsigned short*)&l1 << 16);
            }
        }
#pragma unroll
        for (int ch = 0; ch < 4; ch++) {
#pragma unroll
            for (int r = 0; r < 4; r++) {
                int gate = gbase + mt * 16 + gr + ((r & 1) ? 8 : 0);
                int k = ch * 16 + tg * 2 + ((r >> 1) ? 8 : 0);
                float w0 = Wih[gate * FF + k], w1 = Wih[gate * FF + k + 1];
                __nv_bfloat16 h0 = __float2bfloat16(w0), h1 = __float2bfloat16(w1);
                __nv_bfloat16 l0 = __float2bfloat16(w0 - __bfloat162float(h0));
                __nv_bfloat16 l1 = __float2bfloat16(w1 - __bfloat162float(h1));
                iH[mt][ch][r] = (uint32_t)*(unsigned short*)&h0 | ((uint32_t)*(unsigned short*)&h1 << 16);
                iL[mt][ch][r] = (uint32_t)*(unsigned short*)&l0 | ((uint32_t)*(unsigned short*)&l1 << 16);
            }
        }
    }
    // biases for my 4 (mt, m) gate positions
    float bias[2][2];
#pragma unroll
    for (int mt = 0; mt < 2; mt++) {
        bias[mt][0] = bih[gbase + mt * 16 + gr]     + bhh[gbase + mt * 16 + gr];
        bias[mt][1] = bih[gbase + mt * 16 + gr + 8] + bhh[gbase + mt * 16 + gr + 8];
    }

    // peer smem
    uint32_t peerHHI, peerHLO;
    {
        uint32_t la = (uint32_t)__cvta_generic_to_shared(&hhi[0][0][0]);
        asm("mapa.shared::cluster.u32 %0, %1, %2;" : "=r"(peerHHI) : "r"(la), "r"(1u - rank));
        la = (uint32_t)__cvta_generic_to_shared(&hlo[0][0][0]);
        asm("mapa.shared::cluster.u32 %0, %1, %2;" : "=r"(peerHLO) : "r"(la), "r"(1u - rank));
    }

    // init: zero h, load x(step 0) into xbuf[0]
    for (int i = t; i < 2 * 8 * 136; i += 256) {
        ((unsigned short*)hhi)[i] = 0;
        ((unsigned short*)hlo)[i] = 0;
    }
    {
        int row = t >> 5, f = (t & 31) * 2;
        float2 v = *(const float2*)(x + ((size_t)(row0 + row) * TT + 0) * FF + f);
        __nv_bfloat16 h0 = __float2bfloat16(v.x), h1 = __float2bfloat16(v.y);
        xhi[0][row][f]     = *(unsigned short*)&h0;
        xhi[0][row][f + 1] = *(unsigned short*)&h1;
        __nv_bfloat16 l0 = __float2bfloat16(v.x - __bfloat162float(h0));
        __nv_bfloat16 l1 = __float2bfloat16(v.y - __bfloat162float(h1));
        xlo[0][row][f]     = *(unsigned short*)&l0;
        xlo[0][row][f + 1] = *(unsigned short*)&l1;
    }
    float c0 = 0.f, c1 = 0.f;   // c for my 2 pointwise pairs
    const int n0 = tg * 2;
    __syncthreads();
    asm volatile("barrier.cluster.arrive.aligned;" ::: "memory");
    asm volatile("barrier.cluster.wait.aligned;"   ::: "memory");

    for (int step = 0; step < TT; step++) {
        const int par = step & 1;

        // prefetch x(step+1) (coalesced; consumed in epilogue)
        float2 xpre = make_float2(0.f, 0.f);
        const int xrow = t >> 5, xf = (t & 31) * 2;
        if (step + 1 < TT)
            xpre = *(const float2*)(x + ((size_t)(row0 + xrow) * TT + step + 1) * FF + xf);

        // ---- MMA: D[mt] = Wih*x (3 terms) + Whh*h (3 terms)
        float dA[2][4] = {{0,0,0,0},{0,0,0,0}};
        float dB[2][4] = {{0,0,0,0},{0,0,0,0}};
#pragma unroll
        for (int ch = 0; ch < 4; ch++) {
            uint32_t bh0 = *(const uint32_t*)&xhi[par][gr][ch * 16 + tg * 2];
            uint32_t bh1 = *(const uint32_t*)&xhi[par][gr][ch * 16 + 8 + tg * 2];
            uint32_t bl0 = *(const uint32_t*)&xlo[par][gr][ch * 16 + tg * 2];
            uint32_t bl1 = *(const uint32_t*)&xlo[par][gr][ch * 16 + 8 + tg * 2];
#pragma unroll
            for (int mt = 0; mt < 2; mt++) {
                MMA16816(dA[mt][0], dA[mt][1], dA[mt][2], dA[mt][3], iH[mt][ch], bh0, bh1);
                MMA16816(dB[mt][0], dB[mt][1], dB[mt][2], dB[mt][3], iH[mt][ch], bl0, bl1);
                MMA16816(dB[mt][0], dB[mt][1], dB[mt][2], dB[mt][3], iL[mt][ch], bh0, bh1);
            }
        }
#pragma unroll
        for (int ch = 0; ch < 8; ch++) {
            uint32_t bh0 = *(const uint32_t*)&hhi[par][gr][ch * 16 + tg * 2];
            uint32_t bh1 = *(const uint32_t*)&hhi[par][gr][ch * 16 + 8 + tg * 2];
            uint32_t bl0 = *(const uint32_t*)&hlo[par][gr][ch * 16 + tg * 2];
            uint32_t bl1 = *(const uint32_t*)&hlo[par][gr][ch * 16 + 8 + tg * 2];
#pragma unroll
            for (int mt = 0; mt < 2; mt++) {
                MMA16816(dA[mt][0], dA[mt][1], dA[mt][2], dA[mt][3], aH[mt][ch], bh0, bh1);
                MMA16816(dB[mt][0], dB[mt][1], dB[mt][2], dB[mt][3], aH[mt][ch], bl0, bl1);
                MMA16816(dB[mt][0], dB[mt][1], dB[mt][2], dB[mt][3], aL[mt][ch], bh0, bh1);
            }
        }

        // ---- activations -> actbuf
#pragma unroll
        for (int mt = 0; mt < 2; mt++) {
            float v00 = dA[mt][0] + dB[mt][0] + bias[mt][0];
            float v01 = dA[mt][1] + dB[mt][1] + bias[mt][0];
            float v10 = dA[mt][2] + dB[mt][2] + bias[mt][1];
            float v11 = dA[mt][3] + dB[mt][3] + bias[mt][1];
            if (type == 2) {
                v00 = ftanh(v00); v01 = ftanh(v01); v10 = ftanh(v10); v11 = ftanh(v11);
            } else {
                v00 = fsigm(v00); v01 = fsigm(v01); v10 = fsigm(v10); v11 = fsigm(v11);
            }
            int j = jb + mt * 16 + gr;
            actbuf[type][j][n0]         = v00;
            actbuf[type][j][n0 + 1]     = v01;
            actbuf[type][j + 8][n0]     = v10;
            actbuf[type][j + 8][n0 + 1] = v11;
        }
        __syncthreads();

        // ---- xbuf write for step+1 (parity buffer, safe)
        {
            const int wb = (step + 1) & 1;
            __nv_bfloat16 h0 = __float2bfloat16(xpre.x), h1 = __float2bfloat16(xpre.y);
            xhi[wb][xrow][xf]     = *(unsigned short*)&h0;
            xhi[wb][xrow][xf + 1] = *(unsigned short*)&h1;
            __nv_bfloat16 l0 = __float2bfloat16(xpre.x - __bfloat162float(h0));
            __nv_bfloat16 l1 = __float2bfloat16(xpre.y - __bfloat162float(h1));
            xlo[wb][xrow][xf]     = *(unsigned short*)&l0;
            xlo[wb][xrow][xf + 1] = *(unsigned short*)&l1;
        }

        // ---- pointwise: 2 (j,n) pairs per thread
        const int wpar = par ^ 1;
#pragma unroll
        for (int p = 0; p < 2; p++) {
            int idx = t + p * 256;
            int pj = idx >> 3, pn = idx & 7;
            int jglob = 64 * (int)rank + pj;
            float iv = actbuf[0][pj][pn];
            float fv = actbuf[1][pj][pn];
            float gv = actbuf[2][pj][pn];
            float ov = actbuf[3][pj][pn];
            float& cc = p ? c1 : c0;
            cc = fv * cc + iv * gv;
            float h = ov * ftanh(cc);
            g_hs[((size_t)(row0 + pn) * TT + step) * HH + jglob] = h;

            __nv_bfloat16 hh = __float2bfloat16(h);
            __nv_bfloat16 hl = __float2bfloat16(h - __bfloat162float(hh));
            unsigned short hb = *(unsigned short*)&hh, lb = *(unsigned short*)&hl;
            hhi[wpar][pn][jglob] = hb;
            hlo[wpar][pn][jglob] = lb;
            uint32_t off = (uint32_t)(((wpar * 8 + pn) * 136 + jglob) * 2);
            asm volatile("st.shared::cluster.b16 [%0], %1;" :: "r"(peerHHI + off), "h"(hb) : "memory");
            asm volatile("st.shared::cluster.b16 [%0], %1;" :: "r"(peerHLO + off), "h"(lb) : "memory");
        }
        // cluster sync: orders h/x/actbuf for next step (subsumes CTA sync)
        asm volatile("barrier.cluster.arrive.aligned;" ::: "memory");
        asm volatile("barrier.cluster.wait.aligned;"   ::: "memory");
    }
}

// ---------------- K3 (R3 verbatim) ----------------
__global__ __launch_bounds__(256) void k3_proj(
    const float* __restrict__ Wout, float* __restrict__ out)
{
    __shared__ __align__(16) float hs_s[32][128];
    __shared__ __align__(16) float ws[128][64];
    const int bt0 = blockIdx.x * 32, t = threadIdx.x;
    for (int i = t; i < 1024; i += 256) {
        int row = i >> 5, q = i & 31;
        ((float4*)hs_s[row])[q] = ((const float4*)(g_hs + (size_t)(bt0 + row) * HH))[q];
    }
    for (int i = t; i < 2048; i += 256) {
        int f = i >> 5, kq = i & 31;
        float4 v = ((const float4*)(Wout + (size_t)f * HH))[kq];
        int k = kq * 4;
        ws[k][f] = v.x; ws[k + 1][f] = v.y; ws[k + 2][f] = v.z; ws[k + 3][f] = v.w;
    }
    __syncthreads();
    const int tf = t & 15, tr = t >> 4;
    float4 acc0 = make_float4(0.f, 0.f, 0.f, 0.f), acc1 = acc0;
#pragma unroll
    for (int k = 0; k < 128; k++) {
        float4 w4 = *(float4*)&ws[k][tf * 4];
        float h0 = hs_s[tr][k], h1 = hs_s[tr + 16][k];
        acc0.x += h0 * w4.x; acc0.y += h0 * w4.y; acc0.z += h0 * w4.z; acc0.w += h0 * w4.w;
        acc1.x += h1 * w4.x; acc1.y += h1 * w4.y; acc1.z += h1 * w4.z; acc1.w += h1 * w4.w;
    }
    *(float4*)(out + (size_t)(bt0 + tr) * FF + tf * 4) = acc0;
    *(float4*)(out + (size_t)(bt0 + tr + 16) * FF + tf * 4) = acc1;
}

extern "C" void kernel_launch(void* const* d_in, const int* in_sizes, int n_in,
                              void* d_out, int out_size)
{
    const float* x    = (const float*)d_in[0];
    const float* Wih  = (const float*)d_in[1];
    const float* Whh  = (const float*)d_in[2];
    const float* bih  = (const float*)d_in[3];
    const float* bhh  = (const float*)d_in[4];
    const float* Wout = (const float*)d_in[5];
    float* out = (float*)d_out;
    (void)in_sizes; (void)n_in; (void)out_size;

    k2_lstm_fused<<<64, 256>>>(x, Wih, Whh, bih, bhh);
    k3_proj<<<(BB * TT) / 32, 256>>>(Wout, out);
}